// round 3
// baseline (speedup 1.0000x reference)
#include <cuda_runtime.h>
#include <math.h>

#define BB 8
#define NN 2048
#define DD 128

// ---------------- scratch (static device globals; no allocation) ----------
__device__ float g_H1[BB*NN*DD];
__device__ float g_H2[BB*NN*DD];
__device__ float g_V1[BB*NN*DD];
__device__ float g_V2[BB*NN*DD];
__device__ float g_S[(size_t)BB*NN*NN];          // 134 MB
__device__ float g_rmax[BB*NN], g_rzi[BB*NN];    // row stats (max, 1/sumexp)
__device__ float g_cmax[BB*NN], g_czi[BB*NN];    // col stats
__device__ float g_N12[BB*NN*DD], g_N21[BB*NN*DD];
__device__ float g_pmax[BB*8*NN], g_pz[BB*8*NN]; // col-stat partials

#define BM 128
#define BN 128
#define BK 32
#define ASTR (BM+4)

// ---------------- generic TN GEMM: C[r,c] = sum_k A[r,k]*B[c,k] ----------
// EPI: 0 = plain store, 1 = +bias then leaky_relu(0.01)
template<int EPI>
__global__ __launch_bounds__(256,1) void gemm_tn(
    const float* __restrict__ A, const float* __restrict__ Bmat,
    float* __restrict__ C, const float* __restrict__ bias,
    int K, int ldA, int ldB, int ldC,
    long strideA, long strideB, long strideC)
{
    __shared__ float As[BK][ASTR];
    __shared__ float Bs[BK][ASTR];
    int bz = blockIdx.z;
    const float* Ab = A + (long)bz*strideA + (long)blockIdx.x*BM*ldA;
    const float* Bb = Bmat + (long)bz*strideB + (long)blockIdx.y*BN*ldB;
    float* Cb = C + (long)bz*strideC + (long)blockIdx.x*BM*ldC + blockIdx.y*BN;
    int tid = threadIdx.x;
    int tx = tid & 15, ty = tid >> 4;
    float acc[8][8];
#pragma unroll
    for (int i=0;i<8;i++)
#pragma unroll
        for (int j=0;j<8;j++) acc[i][j]=0.f;

    for (int k0=0;k0<K;k0+=BK) {
#pragma unroll
        for (int i=0;i<4;i++) {
            int slot = tid + i*256;
            int row = slot >> 3, c8 = slot & 7;
            float4 va = *(const float4*)(Ab + (long)row*ldA + k0 + c8*4);
            As[c8*4+0][row]=va.x; As[c8*4+1][row]=va.y;
            As[c8*4+2][row]=va.z; As[c8*4+3][row]=va.w;
            float4 vb = *(const float4*)(Bb + (long)row*ldB + k0 + c8*4);
            Bs[c8*4+0][row]=vb.x; Bs[c8*4+1][row]=vb.y;
            Bs[c8*4+2][row]=vb.z; Bs[c8*4+3][row]=vb.w;
        }
        __syncthreads();
#pragma unroll
        for (int kk=0;kk<BK;kk++) {
            float a[8], b[8];
            *(float4*)(a  ) = *(float4*)&As[kk][ty*8];
            *(float4*)(a+4) = *(float4*)&As[kk][ty*8+4];
            *(float4*)(b  ) = *(float4*)&Bs[kk][tx*8];
            *(float4*)(b+4) = *(float4*)&Bs[kk][tx*8+4];
#pragma unroll
            for (int i=0;i<8;i++)
#pragma unroll
                for (int j=0;j<8;j++) acc[i][j] += a[i]*b[j];
        }
        __syncthreads();
    }
#pragma unroll
    for (int i=0;i<8;i++) {
        int r = ty*8+i;
#pragma unroll
        for (int j=0;j<8;j+=4) {
            float4 v;
            v.x=acc[i][j]; v.y=acc[i][j+1]; v.z=acc[i][j+2]; v.w=acc[i][j+3];
            if (EPI==1) {
                int c = blockIdx.y*BN + tx*8 + j;
                v.x += bias[c];   v.y += bias[c+1];
                v.z += bias[c+2]; v.w += bias[c+3];
                v.x = v.x>0.f? v.x : 0.01f*v.x;
                v.y = v.y>0.f? v.y : 0.01f*v.y;
                v.z = v.z>0.f? v.z : 0.01f*v.z;
                v.w = v.w>0.f? v.w : 0.01f*v.w;
            }
            *(float4*)(Cb + (long)r*ldC + tx*8 + j) = v;
        }
    }
}

// ---------------- row stats: per row n of S[b]: max_m, 1/sum_m exp --------
__global__ void row_stats(const float* __restrict__ S,
                          float* __restrict__ rmax, float* __restrict__ rzi)
{
    int warp = threadIdx.x >> 5, lane = threadIdx.x & 31;
    int row = blockIdx.x*8 + warp;                 // global row in [0, B*N)
    const float* p = S + (size_t)row * NN;
    float mx = -1e30f, z = 0.f;
    for (int m = lane; m < NN; m += 32) {
        float v = p[m];
        float nm = fmaxf(mx, v);
        z = z*__expf(mx-nm) + __expf(v-nm);
        mx = nm;
    }
#pragma unroll
    for (int off=16; off>0; off>>=1) {
        float om = __shfl_xor_sync(0xffffffffu, mx, off);
        float oz = __shfl_xor_sync(0xffffffffu, z,  off);
        float nm = fmaxf(mx, om);
        z = z*__expf(mx-nm) + oz*__expf(om-nm);
        mx = nm;
    }
    if (lane==0) { rmax[row]=mx; rzi[row]=1.f/z; }
}

// ---------------- col stats: partial over 256-row chunks ------------------
__global__ void col_stats_partial(const float* __restrict__ S,
                                  float* __restrict__ pmax, float* __restrict__ pz)
{
    int b = blockIdx.z;
    int m = blockIdx.x*128 + threadIdx.x;
    int n0 = blockIdx.y * (NN/8);
    const float* base = S + (size_t)b*NN*NN + (size_t)n0*NN + m;
    float mx = -1e30f, z = 0.f;
#pragma unroll 4
    for (int i=0;i<NN/8;i++) {
        float v = base[(size_t)i*NN];
        float nm = fmaxf(mx, v);
        z = z*__expf(mx-nm) + __expf(v-nm);
        mx = nm;
    }
    pmax[(b*8+blockIdx.y)*NN + m] = mx;
    pz  [(b*8+blockIdx.y)*NN + m] = z;
}

__global__ void col_stats_combine(const float* __restrict__ pmax,
                                  const float* __restrict__ pz,
                                  float* __restrict__ cmax, float* __restrict__ czi)
{
    int idx = blockIdx.x*256 + threadIdx.x;        // [0, B*N)
    int b = idx >> 11, m = idx & (NN-1);
    float mx = -1e30f, z = 0.f;
#pragma unroll
    for (int c=0;c<8;c++) {
        float om = pmax[(b*8+c)*NN + m];
        float oz = pz  [(b*8+c)*NN + m];
        float nm = fmaxf(mx, om);
        z = z*__expf(mx-nm) + oz*__expf(om-nm);
        mx = nm;
    }
    cmax[idx]=mx; czi[idx]=1.f/z;
}

// ---------------- attention AV GEMM ---------------------------------------
// MODE 1: Out[n,k] = sum_m exp(S[n,m]-cmax[m]) * (V2[m,k]*czi[m])
// MODE 2: Out[m,k] = sum_n exp(S[n,m]-rmax[n]) * (V1[n,k]*rzi[n])
template<int MODE>
__global__ __launch_bounds__(256,1) void attn_av(
    const float* __restrict__ S, const float* __restrict__ V,
    const float* __restrict__ mx, const float* __restrict__ zi,
    float* __restrict__ Out)
{
    __shared__ float As[BK][ASTR];
    __shared__ float Bs[BK][ASTR];
    int b = blockIdx.z;
    const float* Sb  = S  + (size_t)b*NN*NN;
    const float* Vb  = V  + (size_t)b*NN*DD;
    const float* mxb = mx + b*NN;
    const float* zib = zi + b*NN;
    int rb = blockIdx.x*BM;
    float* Ob = Out + (size_t)b*NN*DD + (size_t)rb*DD;
    int tid=threadIdx.x, tx=tid&15, ty=tid>>4;
    float acc[8][8];
#pragma unroll
    for (int i=0;i<8;i++)
#pragma unroll
        for (int j=0;j<8;j++) acc[i][j]=0.f;

    for (int p0=0;p0<NN;p0+=BK) {
        if (MODE==1) {
            // slab: 128 rows (n) x 32 cols (m=p); transpose-scatter, exp on the fly
#pragma unroll
            for (int i=0;i<4;i++) {
                int slot = tid + i*256;
                int row = slot >> 3, c8 = slot & 7;
                float4 v  = *(const float4*)(Sb + (size_t)(rb+row)*NN + p0 + c8*4);
                float4 m4 = *(const float4*)(mxb + p0 + c8*4);
                As[c8*4+0][row] = __expf(v.x - m4.x);
                As[c8*4+1][row] = __expf(v.y - m4.y);
                As[c8*4+2][row] = __expf(v.z - m4.z);
                As[c8*4+3][row] = __expf(v.w - m4.w);
            }
        } else {
            // slab: 32 rows (n=p) x 128 cols (m); direct, exp on the fly
#pragma unroll
            for (int i=0;i<4;i++) {
                int slot = tid + i*256;
                int row = slot >> 5, c32 = slot & 31;
                float4 v = *(const float4*)(Sb + (size_t)(p0+row)*NN + rb + c32*4);
                float m  = __ldg(mxb + p0 + row);
                float4 e;
                e.x=__expf(v.x-m); e.y=__expf(v.y-m);
                e.z=__expf(v.z-m); e.w=__expf(v.w-m);
                *(float4*)&As[row][c32*4] = e;
            }
        }
        // B slab: 32 rows (p) x 128 cols (k), scaled by 1/Z[p]
#pragma unroll
        for (int i=0;i<4;i++) {
            int slot = tid + i*256;
            int row = slot >> 5, c32 = slot & 31;
            float4 v = *(const float4*)(Vb + (size_t)(p0+row)*DD + c32*4);
            float z  = __ldg(zib + p0 + row);
            v.x*=z; v.y*=z; v.z*=z; v.w*=z;
            *(float4*)&Bs[row][c32*4] = v;
        }
        __syncthreads();
#pragma unroll
        for (int kk=0;kk<BK;kk++) {
            float a[8], b2[8];
            *(float4*)(a  ) = *(float4*)&As[kk][ty*8];
            *(float4*)(a+4) = *(float4*)&As[kk][ty*8+4];
            *(float4*)(b2  ) = *(float4*)&Bs[kk][tx*8];
            *(float4*)(b2+4) = *(float4*)&Bs[kk][tx*8+4];
#pragma unroll
            for (int i=0;i<8;i++)
#pragma unroll
                for (int j=0;j<8;j++) acc[i][j] += a[i]*b2[j];
        }
        __syncthreads();
    }
#pragma unroll
    for (int i=0;i<8;i++) {
        int r = ty*8+i;
#pragma unroll
        for (int j=0;j<8;j+=4) {
            float4 v;
            v.x=acc[i][j]; v.y=acc[i][j+1]; v.z=acc[i][j+2]; v.w=acc[i][j+3];
            *(float4*)(Ob + (size_t)r*DD + tx*8 + j) = v;
        }
    }
}

// ---------------- launch ---------------------------------------------------
extern "C" void kernel_launch(void* const* d_in, const int* in_sizes, int n_in,
                              void* d_out, int out_size)
{
    const float* x1 = (const float*)d_in[0];
    const float* x2 = (const float*)d_in[1];
    const float* Wk = (const float*)d_in[2];
    const float* Wv = (const float*)d_in[3];
    const float* Wo = (const float*)d_in[4];
    const float* bo = (const float*)d_in[5];
    float* msg1 = (float*)d_out;
    float* msg2 = msg1 + (size_t)BB*NN*DD;

    float *H1,*H2,*V1,*V2,*S,*rmax,*rzi,*cmax,*czi,*N12,*N21,*pmax,*pz;
    cudaGetSymbolAddress((void**)&H1,  g_H1);
    cudaGetSymbolAddress((void**)&H2,  g_H2);
    cudaGetSymbolAddress((void**)&V1,  g_V1);
    cudaGetSymbolAddress((void**)&V2,  g_V2);
    cudaGetSymbolAddress((void**)&S,   g_S);
    cudaGetSymbolAddress((void**)&rmax,g_rmax);
    cudaGetSymbolAddress((void**)&rzi, g_rzi);
    cudaGetSymbolAddress((void**)&cmax,g_cmax);
    cudaGetSymbolAddress((void**)&czi, g_czi);
    cudaGetSymbolAddress((void**)&N12, g_N12);
    cudaGetSymbolAddress((void**)&N21, g_N21);
    cudaGetSymbolAddress((void**)&pmax,g_pmax);
    cudaGetSymbolAddress((void**)&pz,  g_pz);

    dim3 thr(256);

    // 1) projections: H1=x1@Wk^T, H2=x2@Wk^T, V1=x1@Wv^T, V2=x2@Wv^T
    dim3 gp(128,1,1);   // M = B*N = 16384 rows
    gemm_tn<0><<<gp,thr>>>(x1,Wk,H1,nullptr,DD,DD,DD,DD,0,0,0);
    gemm_tn<0><<<gp,thr>>>(x2,Wk,H2,nullptr,DD,DD,DD,DD,0,0,0);
    gemm_tn<0><<<gp,thr>>>(x1,Wv,V1,nullptr,DD,DD,DD,DD,0,0,0);
    gemm_tn<0><<<gp,thr>>>(x2,Wv,V2,nullptr,DD,DD,DD,DD,0,0,0);

    // 2) S[b] = H1[b] @ H2[b]^T
    dim3 gs(16,16,8);
    gemm_tn<0><<<gs,thr>>>(H1,H2,S,nullptr,DD,DD,DD,NN,
                           (long)NN*DD,(long)NN*DD,(long)NN*NN);

    // 3) softmax stats
    row_stats<<<2048,256>>>(S,rmax,rzi);
    col_stats_partial<<<dim3(16,8,8),128>>>(S,pmax,pz);
    col_stats_combine<<<64,256>>>(pmax,pz,cmax,czi);

    // 4) attention-weighted sums
    dim3 ga(16,1,8);
    attn_av<1><<<ga,thr>>>(S,V2,cmax,czi,N12);
    attn_av<2><<<ga,thr>>>(S,V1,rmax,rzi,N21);

    // 5) output projection + bias + leaky relu
    gemm_tn<1><<<gp,thr>>>(N12,Wo,msg1,bo,DD,DD,DD,DD,0,0,0);
    gemm_tn<1><<<gp,thr>>>(N21,Wo,msg2,bo,DD,DD,DD,DD,0,0,0);
}

// round 4
// speedup vs baseline: 1.3903x; 1.3903x over previous
#include <cuda_runtime.h>
#include <cuda_bf16.h>
#include <math.h>
#include <stdint.h>

#define BB 8
#define NN 2048
#define DD 128
#define KCAT 384

// ---------------- scratch (static device globals; no allocation) ----------
__device__ __nv_bfloat16 g_H1cat[(size_t)BB*NN*KCAT];  // [hi|hi|lo]
__device__ __nv_bfloat16 g_H2cat[(size_t)BB*NN*KCAT];  // [hi|lo|hi]
__device__ float g_V1[BB*NN*DD];
__device__ float g_V2[BB*NN*DD];
__device__ __nv_bfloat16 g_Vt1h[(size_t)BB*DD*NN], g_Vt1l[(size_t)BB*DD*NN];
__device__ __nv_bfloat16 g_Vt2h[(size_t)BB*DD*NN], g_Vt2l[(size_t)BB*DD*NN];
__device__ float g_S[(size_t)BB*NN*NN];          // 134 MB
__device__ float g_rmax[BB*NN], g_rzi[BB*NN];
__device__ float g_cmax[BB*NN], g_czi[BB*NN];
__device__ float g_N12[BB*NN*DD], g_N21[BB*NN*DD];
__device__ float g_pmax[BB*8*NN], g_pz[BB*8*NN];

// ---------------- mma / ldmatrix helpers ----------------------------------
__device__ __forceinline__ void mma16816(float* d, const uint32_t* a, const uint32_t* b){
    asm volatile(
        "mma.sync.aligned.m16n8k16.row.col.f32.bf16.bf16.f32 "
        "{%0,%1,%2,%3},{%4,%5,%6,%7},{%8,%9},{%0,%1,%2,%3};\n"
        : "+f"(d[0]),"+f"(d[1]),"+f"(d[2]),"+f"(d[3])
        : "r"(a[0]),"r"(a[1]),"r"(a[2]),"r"(a[3]),"r"(b[0]),"r"(b[1]));
}
__device__ __forceinline__ void ldsm4(uint32_t* r, uint32_t addr){
    asm volatile("ldmatrix.sync.aligned.m8n8.x4.shared.b16 {%0,%1,%2,%3},[%4];\n"
        :"=r"(r[0]),"=r"(r[1]),"=r"(r[2]),"=r"(r[3]):"r"(addr));
}
__device__ __forceinline__ void ldsm4t(uint32_t* r, uint32_t addr){
    asm volatile("ldmatrix.sync.aligned.m8n8.x4.trans.shared.b16 {%0,%1,%2,%3},[%4];\n"
        :"=r"(r[0]),"=r"(r[1]),"=r"(r[2]),"=r"(r[3]):"r"(addr));
}
__device__ __forceinline__ uint32_t cvta_s(const void* p){
    return (uint32_t)__cvta_generic_to_shared(p);
}

// ---------------- fp32 SIMT GEMM (projections / epilogue) ------------------
#define BM 128
#define BN 128
#define BK 32
#define ASTR (BM+4)

template<int EPI>
__global__ __launch_bounds__(256,1) void gemm_tn(
    const float* __restrict__ A, const float* __restrict__ Bmat,
    float* __restrict__ C, const float* __restrict__ bias,
    int K, int ldA, int ldB, int ldC,
    long strideA, long strideB, long strideC)
{
    __shared__ float As[BK][ASTR];
    __shared__ float Bs[BK][ASTR];
    int bz = blockIdx.z;
    const float* Ab = A + (long)bz*strideA + (long)blockIdx.x*BM*ldA;
    const float* Bb = Bmat + (long)bz*strideB + (long)blockIdx.y*BN*ldB;
    float* Cb = C + (long)bz*strideC + (long)blockIdx.x*BM*ldC + blockIdx.y*BN;
    int tid = threadIdx.x;
    int tx = tid & 15, ty = tid >> 4;
    float acc[8][8];
#pragma unroll
    for (int i=0;i<8;i++)
#pragma unroll
        for (int j=0;j<8;j++) acc[i][j]=0.f;

    for (int k0=0;k0<K;k0+=BK) {
#pragma unroll
        for (int i=0;i<4;i++) {
            int slot = tid + i*256;
            int row = slot >> 3, c8 = slot & 7;
            float4 va = *(const float4*)(Ab + (long)row*ldA + k0 + c8*4);
            As[c8*4+0][row]=va.x; As[c8*4+1][row]=va.y;
            As[c8*4+2][row]=va.z; As[c8*4+3][row]=va.w;
            float4 vb = *(const float4*)(Bb + (long)row*ldB + k0 + c8*4);
            Bs[c8*4+0][row]=vb.x; Bs[c8*4+1][row]=vb.y;
            Bs[c8*4+2][row]=vb.z; Bs[c8*4+3][row]=vb.w;
        }
        __syncthreads();
#pragma unroll
        for (int kk=0;kk<BK;kk++) {
            float a[8], b[8];
            *(float4*)(a  ) = *(float4*)&As[kk][ty*8];
            *(float4*)(a+4) = *(float4*)&As[kk][ty*8+4];
            *(float4*)(b  ) = *(float4*)&Bs[kk][tx*8];
            *(float4*)(b+4) = *(float4*)&Bs[kk][tx*8+4];
#pragma unroll
            for (int i=0;i<8;i++)
#pragma unroll
                for (int j=0;j<8;j++) acc[i][j] += a[i]*b[j];
        }
        __syncthreads();
    }
#pragma unroll
    for (int i=0;i<8;i++) {
        int r = ty*8+i;
#pragma unroll
        for (int j=0;j<8;j+=4) {
            float4 v;
            v.x=acc[i][j]; v.y=acc[i][j+1]; v.z=acc[i][j+2]; v.w=acc[i][j+3];
            if (EPI==1) {
                int c = blockIdx.y*BN + tx*8 + j;
                v.x += bias[c];   v.y += bias[c+1];
                v.z += bias[c+2]; v.w += bias[c+3];
                v.x = v.x>0.f? v.x : 0.01f*v.x;
                v.y = v.y>0.f? v.y : 0.01f*v.y;
                v.z = v.z>0.f? v.z : 0.01f*v.z;
                v.w = v.w>0.f? v.w : 0.01f*v.w;
            }
            *(float4*)(Cb + (long)r*ldC + tx*8 + j) = v;
        }
    }
}

// ---------------- projection + hi/lo split into cat layout -----------------
// ORDER 0 (A-role): [hi | hi | lo];  ORDER 1 (B-role): [hi | lo | hi]
template<int ORDER>
__global__ __launch_bounds__(256,1) void proj_cat(
    const float* __restrict__ A, const float* __restrict__ W,
    __nv_bfloat16* __restrict__ Hcat)
{
    __shared__ float As[BK][ASTR];
    __shared__ float Bs[BK][ASTR];
    const float* Ab = A + (long)blockIdx.x*BM*DD;
    __nv_bfloat16* Cb = Hcat + (size_t)blockIdx.x*BM*KCAT;
    int tid = threadIdx.x;
    int tx = tid & 15, ty = tid >> 4;
    float acc[8][8];
#pragma unroll
    for (int i=0;i<8;i++)
#pragma unroll
        for (int j=0;j<8;j++) acc[i][j]=0.f;

    for (int k0=0;k0<DD;k0+=BK) {
#pragma unroll
        for (int i=0;i<4;i++) {
            int slot = tid + i*256;
            int row = slot >> 3, c8 = slot & 7;
            float4 va = *(const float4*)(Ab + (long)row*DD + k0 + c8*4);
            As[c8*4+0][row]=va.x; As[c8*4+1][row]=va.y;
            As[c8*4+2][row]=va.z; As[c8*4+3][row]=va.w;
            float4 vb = *(const float4*)(W + (long)row*DD + k0 + c8*4);
            Bs[c8*4+0][row]=vb.x; Bs[c8*4+1][row]=vb.y;
            Bs[c8*4+2][row]=vb.z; Bs[c8*4+3][row]=vb.w;
        }
        __syncthreads();
#pragma unroll
        for (int kk=0;kk<BK;kk++) {
            float a[8], b[8];
            *(float4*)(a  ) = *(float4*)&As[kk][ty*8];
            *(float4*)(a+4) = *(float4*)&As[kk][ty*8+4];
            *(float4*)(b  ) = *(float4*)&Bs[kk][tx*8];
            *(float4*)(b+4) = *(float4*)&Bs[kk][tx*8+4];
#pragma unroll
            for (int i=0;i<8;i++)
#pragma unroll
                for (int j=0;j<8;j++) acc[i][j] += a[i]*b[j];
        }
        __syncthreads();
    }
#pragma unroll
    for (int i=0;i<8;i++) {
        int r = ty*8+i;
#pragma unroll
        for (int j=0;j<8;j+=2) {
            float x = acc[i][j], y = acc[i][j+1];
            __nv_bfloat16 hx = __float2bfloat16(x);
            __nv_bfloat16 hy = __float2bfloat16(y);
            __nv_bfloat16 lx = __float2bfloat16(x - __bfloat162float(hx));
            __nv_bfloat16 ly = __float2bfloat16(y - __bfloat162float(hy));
            __nv_bfloat162 hp; hp.x = hx; hp.y = hy;
            __nv_bfloat162 lp; lp.x = lx; lp.y = ly;
            int c = tx*8 + j;
            __nv_bfloat16* base = Cb + (size_t)r*KCAT + c;
            *(__nv_bfloat162*)(base)       = hp;
            *(__nv_bfloat162*)(base + 128) = (ORDER==0) ? hp : lp;
            *(__nv_bfloat162*)(base + 256) = (ORDER==0) ? lp : hp;
        }
    }
}

// ---------------- S = H1cat @ H2cat^T (bf16 tensor, K=384) -----------------
#define STS 72
__global__ __launch_bounds__(256,1) void gemm_s_mma(
    const __nv_bfloat16* __restrict__ Acat,
    const __nv_bfloat16* __restrict__ Bcat,
    float* __restrict__ S)
{
    __shared__ __align__(16) __nv_bfloat16 As[128*STS];
    __shared__ __align__(16) __nv_bfloat16 Bs[128*STS];
    int b = blockIdx.z;
    const __nv_bfloat16* Ab = Acat + (size_t)b*NN*KCAT + (size_t)blockIdx.x*128*KCAT;
    const __nv_bfloat16* Bb = Bcat + (size_t)b*NN*KCAT + (size_t)blockIdx.y*128*KCAT;
    float* Sb = S + (size_t)b*NN*NN + (size_t)blockIdx.x*128*NN + blockIdx.y*128;
    int tid = threadIdx.x, lane = tid & 31, w = tid >> 5;
    int wr = (w>>2)*64, wc = (w&3)*32;
    uint32_t aB = cvta_s(As), bB = cvta_s(Bs);
    int lrow = lane & 15, lcol = (lane>>4)*8;
    float acc[4][4][4];
#pragma unroll
    for (int i=0;i<4;i++)
#pragma unroll
        for (int j=0;j<4;j++)
#pragma unroll
            for (int r=0;r<4;r++) acc[i][j][r]=0.f;

    int row = tid >> 1, part = tid & 1;
    for (int k0=0;k0<KCAT;k0+=64) {
        const int4* ga = (const int4*)(Ab + (size_t)row*KCAT + k0 + part*32);
        const int4* gb = (const int4*)(Bb + (size_t)row*KCAT + k0 + part*32);
        int4* sa = (int4*)(As + row*STS + part*32);
        int4* sb = (int4*)(Bs + row*STS + part*32);
        sa[0]=ga[0]; sa[1]=ga[1]; sa[2]=ga[2]; sa[3]=ga[3];
        sb[0]=gb[0]; sb[1]=gb[1]; sb[2]=gb[2]; sb[3]=gb[3];
        __syncthreads();
#pragma unroll
        for (int ks=0; ks<4; ks++) {
            int kk = ks*16;
            uint32_t af[4][4], bf[2][4];
#pragma unroll
            for (int mi=0;mi<4;mi++)
                ldsm4(af[mi], aB + (uint32_t)(((wr+mi*16+lrow)*STS + kk + lcol)*2));
#pragma unroll
            for (int nj=0;nj<2;nj++)
                ldsm4(bf[nj], bB + (uint32_t)(((wc+nj*16+lrow)*STS + kk + lcol)*2));
#pragma unroll
            for (int mi=0;mi<4;mi++)
#pragma unroll
                for (int ni=0;ni<4;ni++) {
                    uint32_t bb[2] = { bf[ni>>1][ni&1], bf[ni>>1][(ni&1)+2] };
                    mma16816(acc[mi][ni], af[mi], bb);
                }
        }
        __syncthreads();
    }
    int g = lane>>2, tg = lane&3;
#pragma unroll
    for (int mi=0;mi<4;mi++)
#pragma unroll
        for (int ni=0;ni<4;ni++) {
            int r0 = wr + mi*16 + g, c = wc + ni*8 + 2*tg;
            *(float2*)(Sb + (size_t)r0*NN + c)     = make_float2(acc[mi][ni][0], acc[mi][ni][1]);
            *(float2*)(Sb + (size_t)(r0+8)*NN + c) = make_float2(acc[mi][ni][2], acc[mi][ni][3]);
        }
}

// ---------------- softmax stats (unchanged) --------------------------------
__global__ void row_stats(const float* __restrict__ S,
                          float* __restrict__ rmax, float* __restrict__ rzi)
{
    int warp = threadIdx.x >> 5, lane = threadIdx.x & 31;
    int row = blockIdx.x*8 + warp;
    const float* p = S + (size_t)row * NN;
    float mx = -1e30f, z = 0.f;
    for (int m = lane; m < NN; m += 32) {
        float v = p[m];
        float nm = fmaxf(mx, v);
        z = z*__expf(mx-nm) + __expf(v-nm);
        mx = nm;
    }
#pragma unroll
    for (int off=16; off>0; off>>=1) {
        float om = __shfl_xor_sync(0xffffffffu, mx, off);
        float oz = __shfl_xor_sync(0xffffffffu, z,  off);
        float nm = fmaxf(mx, om);
        z = z*__expf(mx-nm) + oz*__expf(om-nm);
        mx = nm;
    }
    if (lane==0) { rmax[row]=mx; rzi[row]=1.f/z; }
}

__global__ void col_stats_partial(const float* __restrict__ S,
                                  float* __restrict__ pmax, float* __restrict__ pz)
{
    int b = blockIdx.z;
    int m = blockIdx.x*128 + threadIdx.x;
    int n0 = blockIdx.y * (NN/8);
    const float* base = S + (size_t)b*NN*NN + (size_t)n0*NN + m;
    float mx = -1e30f, z = 0.f;
#pragma unroll 4
    for (int i=0;i<NN/8;i++) {
        float v = base[(size_t)i*NN];
        float nm = fmaxf(mx, v);
        z = z*__expf(mx-nm) + __expf(v-nm);
        mx = nm;
    }
    pmax[(b*8+blockIdx.y)*NN + m] = mx;
    pz  [(b*8+blockIdx.y)*NN + m] = z;
}

__global__ void col_stats_combine(const float* __restrict__ pmax,
                                  const float* __restrict__ pz,
                                  float* __restrict__ cmax, float* __restrict__ czi)
{
    int idx = blockIdx.x*256 + threadIdx.x;
    int b = idx >> 11, m = idx & (NN-1);
    float mx = -1e30f, z = 0.f;
#pragma unroll
    for (int c=0;c<8;c++) {
        float om = pmax[(b*8+c)*NN + m];
        float oz = pz  [(b*8+c)*NN + m];
        float nm = fmaxf(mx, om);
        z = z*__expf(mx-nm) + oz*__expf(om-nm);
        mx = nm;
    }
    cmax[idx]=mx; czi[idx]=1.f/z;
}

// ---------------- V prep: scale, transpose to [k][m], split hi/lo ----------
__global__ __launch_bounds__(256,1) void vprep(
    const float* __restrict__ V, const float* __restrict__ scale,
    __nv_bfloat16* __restrict__ Vth, __nv_bfloat16* __restrict__ Vtl)
{
    __shared__ float sh[32][132];
    int b = blockIdx.z;
    const float* Vb = V + (size_t)b*NN*DD;
    const float* sb = scale + b*NN;
    int m0 = blockIdx.x*32;
    int tid = threadIdx.x;
    {
        int r = tid>>3, c16 = (tid&7)*16;
        float s = sb[m0+r];
        const float4* g = (const float4*)(Vb + (size_t)(m0+r)*DD + c16);
#pragma unroll
        for (int q=0;q<4;q++) {
            float4 v = g[q];
            v.x*=s; v.y*=s; v.z*=s; v.w*=s;
            *(float4*)&sh[r][c16+q*4] = v;
        }
    }
    __syncthreads();
    {
        int k = tid>>1, half = tid&1;
        union { __nv_bfloat16 bh[16]; int4 v4[2]; } uh, ul;
#pragma unroll
        for (int j=0;j<16;j++) {
            float f = sh[half*16+j][k];
            __nv_bfloat16 h = __float2bfloat16(f);
            uh.bh[j] = h;
            ul.bh[j] = __float2bfloat16(f - __bfloat162float(h));
        }
        __nv_bfloat16* oh = Vth + (size_t)b*DD*NN + (size_t)k*NN + m0 + half*16;
        __nv_bfloat16* ol = Vtl + (size_t)b*DD*NN + (size_t)k*NN + m0 + half*16;
        ((int4*)oh)[0]=uh.v4[0]; ((int4*)oh)[1]=uh.v4[1];
        ((int4*)ol)[0]=ul.v4[0]; ((int4*)ol)[1]=ul.v4[1];
    }
}

// ---------------- AV via tensor cores --------------------------------------
// MODE 1: Out[n,k] = sum_m exp(S[n,m]-mx[m]) * Vt[k][m]   (A natural layout)
// MODE 2: Out[m,k] = sum_n exp(S[n,m]-mx[n]) * Vt[k][n]   (A via ldmatrix.trans)
#define STA 40
#define STT 136
template<int MODE>
__global__ __launch_bounds__(256,1) void attn_av_mma(
    const float* __restrict__ S,
    const __nv_bfloat16* __restrict__ Vth, const __nv_bfloat16* __restrict__ Vtl,
    const float* __restrict__ mx, float* __restrict__ Out)
{
    __shared__ __align__(16) __nv_bfloat16 Ah[5120];
    __shared__ __align__(16) __nv_bfloat16 Al[5120];
    __shared__ __align__(16) __nv_bfloat16 Bh[5120];
    __shared__ __align__(16) __nv_bfloat16 Bl[5120];
    int b = blockIdx.z;
    const float* Sb = S + (size_t)b*NN*NN;
    const __nv_bfloat16* Vhb = Vth + (size_t)b*DD*NN;
    const __nv_bfloat16* Vlb = Vtl + (size_t)b*DD*NN;
    const float* mxb = mx + b*NN;
    int rb = blockIdx.x*128;
    float* Ob = Out + (size_t)b*NN*DD + (size_t)rb*DD;
    int tid = threadIdx.x, lane = tid & 31, w = tid >> 5;
    int wr = (w&3)*32, wc = (w>>2)*64;
    uint32_t aB = cvta_s(Ah), alB = cvta_s(Al), bB = cvta_s(Bh), blB = cvta_s(Bl);
    int lrow = lane & 15, lcol = (lane>>4)*8;
    int trow = (lane&7) + ((lane>>4)<<3);
    int tcol = ((lane>>3)&1)*8;
    float acc[2][8][4];
#pragma unroll
    for (int i=0;i<2;i++)
#pragma unroll
        for (int j=0;j<8;j++)
#pragma unroll
            for (int r=0;r<4;r++) acc[i][j][r]=0.f;

    for (int p0=0;p0<NN;p0+=32) {
        if (MODE==1) {
            int r = tid>>1, cb = (tid&1)*16;
            const float4* g  = (const float4*)(Sb + (size_t)(rb+r)*NN + p0 + cb);
            const float4* mq = (const float4*)(mxb + p0 + cb);
#pragma unroll
            for (int q=0;q<4;q++) {
                float4 v = g[q], m = mq[q];
                float e0=__expf(v.x-m.x), e1=__expf(v.y-m.y);
                float e2=__expf(v.z-m.z), e3=__expf(v.w-m.w);
                __nv_bfloat16 h0=__float2bfloat16(e0), h1=__float2bfloat16(e1);
                __nv_bfloat16 h2=__float2bfloat16(e2), h3=__float2bfloat16(e3);
                __nv_bfloat162 hp0; hp0.x=h0; hp0.y=h1;
                __nv_bfloat162 hp1; hp1.x=h2; hp1.y=h3;
                __nv_bfloat162 lp0; lp0.x=__float2bfloat16(e0-__bfloat162float(h0));
                                    lp0.y=__float2bfloat16(e1-__bfloat162float(h1));
                __nv_bfloat162 lp1; lp1.x=__float2bfloat16(e2-__bfloat162float(h2));
                                    lp1.y=__float2bfloat16(e3-__bfloat162float(h3));
                int off = r*STA + cb + q*4;
                *(__nv_bfloat162*)(Ah+off)   = hp0; *(__nv_bfloat162*)(Ah+off+2) = hp1;
                *(__nv_bfloat162*)(Al+off)   = lp0; *(__nv_bfloat162*)(Al+off+2) = lp1;
            }
        } else {
            int r = tid>>3, cb = (tid&7)*16;
            const float4* g = (const float4*)(Sb + (size_t)(p0+r)*NN + rb + cb);
            float m = __ldg(mxb + p0 + r);
#pragma unroll
            for (int q=0;q<4;q++) {
                float4 v = g[q];
                float e0=__expf(v.x-m), e1=__expf(v.y-m);
                float e2=__expf(v.z-m), e3=__expf(v.w-m);
                __nv_bfloat16 h0=__float2bfloat16(e0), h1=__float2bfloat16(e1);
                __nv_bfloat16 h2=__float2bfloat16(e2), h3=__float2bfloat16(e3);
                __nv_bfloat162 hp0; hp0.x=h0; hp0.y=h1;
                __nv_bfloat162 hp1; hp1.x=h2; hp1.y=h3;
                __nv_bfloat162 lp0; lp0.x=__float2bfloat16(e0-__bfloat162float(h0));
                                    lp0.y=__float2bfloat16(e1-__bfloat162float(h1));
                __nv_bfloat162 lp1; lp1.x=__float2bfloat16(e2-__bfloat162float(h2));
                                    lp1.y=__float2bfloat16(e3-__bfloat162float(h3));
                int off = r*STT + cb + q*4;
                *(__nv_bfloat162*)(Ah+off)   = hp0; *(__nv_bfloat162*)(Ah+off+2) = hp1;
                *(__nv_bfloat162*)(Al+off)   = lp0; *(__nv_bfloat162*)(Al+off+2) = lp1;
            }
        }
        {
            int r = tid>>1, part = tid&1;
            const int4* gh = (const int4*)(Vhb + (size_t)r*NN + p0 + part*16);
            const int4* gl = (const int4*)(Vlb + (size_t)r*NN + p0 + part*16);
            int4* sh = (int4*)(Bh + r*STA + part*16);
            int4* sl = (int4*)(Bl + r*STA + part*16);
            sh[0]=gh[0]; sh[1]=gh[1];
            sl[0]=gl[0]; sl[1]=gl[1];
        }
        __syncthreads();
#pragma unroll
        for (int pass=0; pass<3; pass++) {
            uint32_t aBase = (pass<2) ? aB : alB;
            uint32_t bBase = (pass==1) ? blB : bB;
#pragma unroll
            for (int ks=0; ks<2; ks++) {
                int kk = ks*16;
                uint32_t af[2][4], bf[4][4];
#pragma unroll
                for (int mi=0;mi<2;mi++) {
                    if (MODE==1)
                        ldsm4 (af[mi], aBase + (uint32_t)(((wr+mi*16+lrow)*STA + kk + lcol)*2));
                    else
                        ldsm4t(af[mi], aBase + (uint32_t)(((kk+trow)*STT + wr + mi*16 + tcol)*2));
                }
#pragma unroll
                for (int nj=0;nj<4;nj++)
                    ldsm4(bf[nj], bBase + (uint32_t)(((wc+nj*16+lrow)*STA + kk + lcol)*2));
#pragma unroll
                for (int mi=0;mi<2;mi++)
#pragma unroll
                    for (int ni=0;ni<8;ni++) {
                        uint32_t bb[2] = { bf[ni>>1][ni&1], bf[ni>>1][(ni&1)+2] };
                        mma16816(acc[mi][ni], af[mi], bb);
                    }
            }
        }
        __syncthreads();
    }
    int g = lane>>2, tg = lane&3;
#pragma unroll
    for (int mi=0;mi<2;mi++)
#pragma unroll
        for (int ni=0;ni<8;ni++) {
            int r0 = wr + mi*16 + g, c = wc + ni*8 + 2*tg;
            *(float2*)(Ob + (size_t)r0*DD + c)     = make_float2(acc[mi][ni][0], acc[mi][ni][1]);
            *(float2*)(Ob + (size_t)(r0+8)*DD + c) = make_float2(acc[mi][ni][2], acc[mi][ni][3]);
        }
}

// ---------------- launch ---------------------------------------------------
extern "C" void kernel_launch(void* const* d_in, const int* in_sizes, int n_in,
                              void* d_out, int out_size)
{
    const float* x1 = (const float*)d_in[0];
    const float* x2 = (const float*)d_in[1];
    const float* Wk = (const float*)d_in[2];
    const float* Wv = (const float*)d_in[3];
    const float* Wo = (const float*)d_in[4];
    const float* bo = (const float*)d_in[5];
    float* msg1 = (float*)d_out;
    float* msg2 = msg1 + (size_t)BB*NN*DD;

    __nv_bfloat16 *H1c,*H2c,*Vt1h,*Vt1l,*Vt2h,*Vt2l;
    float *V1,*V2,*S,*rmax,*rzi,*cmax,*czi,*N12,*N21,*pmax,*pz;
    cudaGetSymbolAddress((void**)&H1c, g_H1cat);
    cudaGetSymbolAddress((void**)&H2c, g_H2cat);
    cudaGetSymbolAddress((void**)&V1,  g_V1);
    cudaGetSymbolAddress((void**)&V2,  g_V2);
    cudaGetSymbolAddress((void**)&Vt1h,g_Vt1h);
    cudaGetSymbolAddress((void**)&Vt1l,g_Vt1l);
    cudaGetSymbolAddress((void**)&Vt2h,g_Vt2h);
    cudaGetSymbolAddress((void**)&Vt2l,g_Vt2l);
    cudaGetSymbolAddress((void**)&S,   g_S);
    cudaGetSymbolAddress((void**)&rmax,g_rmax);
    cudaGetSymbolAddress((void**)&rzi, g_rzi);
    cudaGetSymbolAddress((void**)&cmax,g_cmax);
    cudaGetSymbolAddress((void**)&czi, g_czi);
    cudaGetSymbolAddress((void**)&N12, g_N12);
    cudaGetSymbolAddress((void**)&N21, g_N21);
    cudaGetSymbolAddress((void**)&pmax,g_pmax);
    cudaGetSymbolAddress((void**)&pz,  g_pz);

    dim3 thr(256);
    dim3 gp(128,1,1);

    // 1) key projections -> bf16 hi/lo cat layouts; value projections fp32
    proj_cat<0><<<gp,thr>>>(x1, Wk, H1c);
    proj_cat<1><<<gp,thr>>>(x2, Wk, H2c);
    gemm_tn<0><<<gp,thr>>>(x1,Wv,V1,nullptr,DD,DD,DD,DD,0,0,0);
    gemm_tn<0><<<gp,thr>>>(x2,Wv,V2,nullptr,DD,DD,DD,DD,0,0,0);

    // 2) S[b] = H1[b] @ H2[b]^T  (tensor cores, split-K=384)
    gemm_s_mma<<<dim3(16,16,8),thr>>>(H1c, H2c, S);

    // 3) softmax stats
    row_stats<<<2048,256>>>(S,rmax,rzi);
    col_stats_partial<<<dim3(16,8,8),128>>>(S,pmax,pz);
    col_stats_combine<<<64,256>>>(pmax,pz,cmax,czi);

    // 4) V scale+transpose+split, then tensor-core AV
    vprep<<<dim3(64,1,8),thr>>>(V2, czi, Vt2h, Vt2l);
    vprep<<<dim3(64,1,8),thr>>>(V1, rzi, Vt1h, Vt1l);
    attn_av_mma<1><<<dim3(16,1,8),thr>>>(S, Vt2h, Vt2l, cmax, N12);
    attn_av_mma<2><<<dim3(16,1,8),thr>>>(S, Vt1h, Vt1l, rmax, N21);

    // 5) output projection + bias + leaky relu (fp32)
    gemm_tn<1><<<gp,thr>>>(N12,Wo,msg1,bo,DD,DD,DD,DD,0,0,0);
    gemm_tn<1><<<gp,thr>>>(N21,Wo,msg2,bo,DD,DD,DD,DD,0,0,0);
}

// round 6
// speedup vs baseline: 1.5447x; 1.1111x over previous
#include <cuda_runtime.h>
#include <cuda_bf16.h>
#include <math.h>
#include <stdint.h>

#define BB 8
#define NN 2048
#define DD 128
#define KCAT 384
#define CSHIFT 80.0f

// ---------------- scratch (static device globals; no allocation) ----------
__device__ __nv_bfloat16 g_H1cat[(size_t)BB*NN*KCAT];  // [hi|hi|lo]
__device__ __nv_bfloat16 g_H2cat[(size_t)BB*NN*KCAT];  // [hi|lo|hi]
__device__ float g_V1[BB*NN*DD];
__device__ float g_V2[BB*NN*DD];
__device__ __nv_bfloat16 g_Eh[(size_t)BB*NN*NN];       // exp(S-C) hi, 67MB
__device__ __nv_bfloat16 g_El[(size_t)BB*NN*NN];       // exp(S-C) lo, 67MB
__device__ float g_rowp[(size_t)BB*16*NN], g_colp[(size_t)BB*16*NN];
__device__ float g_rzi[BB*NN], g_czi[BB*NN];
__device__ __nv_bfloat16 g_Vt1h[(size_t)BB*DD*NN], g_Vt1l[(size_t)BB*DD*NN];
__device__ __nv_bfloat16 g_Vt2h[(size_t)BB*DD*NN], g_Vt2l[(size_t)BB*DD*NN];
__device__ float g_N12[BB*NN*DD], g_N21[BB*NN*DD];

// ---------------- mma / ldmatrix helpers ----------------------------------
__device__ __forceinline__ void mma16816(float* d, const uint32_t* a, const uint32_t* b){
    asm volatile(
        "mma.sync.aligned.m16n8k16.row.col.f32.bf16.bf16.f32 "
        "{%0,%1,%2,%3},{%4,%5,%6,%7},{%8,%9},{%0,%1,%2,%3};\n"
        : "+f"(d[0]),"+f"(d[1]),"+f"(d[2]),"+f"(d[3])
        : "r"(a[0]),"r"(a[1]),"r"(a[2]),"r"(a[3]),"r"(b[0]),"r"(b[1]));
}
__device__ __forceinline__ void ldsm4(uint32_t* r, uint32_t addr){
    asm volatile("ldmatrix.sync.aligned.m8n8.x4.shared.b16 {%0,%1,%2,%3},[%4];\n"
        :"=r"(r[0]),"=r"(r[1]),"=r"(r[2]),"=r"(r[3]):"r"(addr));
}
__device__ __forceinline__ void ldsm4t(uint32_t* r, uint32_t addr){
    asm volatile("ldmatrix.sync.aligned.m8n8.x4.trans.shared.b16 {%0,%1,%2,%3},[%4];\n"
        :"=r"(r[0]),"=r"(r[1]),"=r"(r[2]),"=r"(r[3]):"r"(addr));
}
__device__ __forceinline__ uint32_t cvta_s(const void* p){
    return (uint32_t)__cvta_generic_to_shared(p);
}
__device__ __forceinline__ void split2(float a, float b,
                                       __nv_bfloat162& hp, __nv_bfloat162& lp){
    __nv_bfloat16 ha=__float2bfloat16(a), hb=__float2bfloat16(b);
    hp.x=ha; hp.y=hb;
    lp.x=__float2bfloat16(a-__bfloat162float(ha));
    lp.y=__float2bfloat16(b-__bfloat162float(hb));
}

// ---------------- fp32 SIMT GEMM (V projections / epilogue) ----------------
#define BM 128
#define BN 128
#define BK 32
#define ASTR (BM+4)

template<int EPI>
__global__ __launch_bounds__(256,1) void gemm_tn(
    const float* __restrict__ A, const float* __restrict__ Bmat,
    float* __restrict__ C, const float* __restrict__ bias)
{
    __shared__ float As[BK][ASTR];
    __shared__ float Bs[BK][ASTR];
    const float* Ab = A + (long)blockIdx.x*BM*DD;
    float* Cb = C + (long)blockIdx.x*BM*DD;
    int tid = threadIdx.x;
    int tx = tid & 15, ty = tid >> 4;
    float acc[8][8];
#pragma unroll
    for (int i=0;i<8;i++)
#pragma unroll
        for (int j=0;j<8;j++) acc[i][j]=0.f;

    for (int k0=0;k0<DD;k0+=BK) {
#pragma unroll
        for (int i=0;i<4;i++) {
            int slot = tid + i*256;
            int row = slot >> 3, c8 = slot & 7;
            float4 va = *(const float4*)(Ab + (long)row*DD + k0 + c8*4);
            As[c8*4+0][row]=va.x; As[c8*4+1][row]=va.y;
            As[c8*4+2][row]=va.z; As[c8*4+3][row]=va.w;
            float4 vb = *(const float4*)(Bmat + (long)row*DD + k0 + c8*4);
            Bs[c8*4+0][row]=vb.x; Bs[c8*4+1][row]=vb.y;
            Bs[c8*4+2][row]=vb.z; Bs[c8*4+3][row]=vb.w;
        }
        __syncthreads();
#pragma unroll
        for (int kk=0;kk<BK;kk++) {
            float a[8], b[8];
            *(float4*)(a  ) = *(float4*)&As[kk][ty*8];
            *(float4*)(a+4) = *(float4*)&As[kk][ty*8+4];
            *(float4*)(b  ) = *(float4*)&Bs[kk][tx*8];
            *(float4*)(b+4) = *(float4*)&Bs[kk][tx*8+4];
#pragma unroll
            for (int i=0;i<8;i++)
#pragma unroll
                for (int j=0;j<8;j++) acc[i][j] += a[i]*b[j];
        }
        __syncthreads();
    }
#pragma unroll
    for (int i=0;i<8;i++) {
        int r = ty*8+i;
#pragma unroll
        for (int j=0;j<8;j+=4) {
            float4 v;
            v.x=acc[i][j]; v.y=acc[i][j+1]; v.z=acc[i][j+2]; v.w=acc[i][j+3];
            if (EPI==1) {
                int c = tx*8 + j;
                v.x += bias[c];   v.y += bias[c+1];
                v.z += bias[c+2]; v.w += bias[c+3];
                v.x = v.x>0.f? v.x : 0.01f*v.x;
                v.y = v.y>0.f? v.y : 0.01f*v.y;
                v.z = v.z>0.f? v.z : 0.01f*v.z;
                v.w = v.w>0.f? v.w : 0.01f*v.w;
            }
            *(float4*)(Cb + (long)r*DD + tx*8 + j) = v;
        }
    }
}

// ---------------- dual projection + hi/lo split into cat layout ------------
// z=0: x1 -> H1cat [hi|hi|lo];  z=1: x2 -> H2cat [hi|lo|hi]
__global__ __launch_bounds__(256,1) void proj_cat_dual(
    const float* __restrict__ X1, const float* __restrict__ X2,
    const float* __restrict__ W,
    __nv_bfloat16* __restrict__ H1c, __nv_bfloat16* __restrict__ H2c)
{
    __shared__ float As[BK][ASTR];
    __shared__ float Bs[BK][ASTR];
    int which = blockIdx.z;
    const float* Ab = (which==0 ? X1 : X2) + (long)blockIdx.x*BM*DD;
    __nv_bfloat16* Cb = (which==0 ? H1c : H2c) + (size_t)blockIdx.x*BM*KCAT;
    int tid = threadIdx.x;
    int tx = tid & 15, ty = tid >> 4;
    float acc[8][8];
#pragma unroll
    for (int i=0;i<8;i++)
#pragma unroll
        for (int j=0;j<8;j++) acc[i][j]=0.f;

    for (int k0=0;k0<DD;k0+=BK) {
#pragma unroll
        for (int i=0;i<4;i++) {
            int slot = tid + i*256;
            int row = slot >> 3, c8 = slot & 7;
            float4 va = *(const float4*)(Ab + (long)row*DD + k0 + c8*4);
            As[c8*4+0][row]=va.x; As[c8*4+1][row]=va.y;
            As[c8*4+2][row]=va.z; As[c8*4+3][row]=va.w;
            float4 vb = *(const float4*)(W + (long)row*DD + k0 + c8*4);
            Bs[c8*4+0][row]=vb.x; Bs[c8*4+1][row]=vb.y;
            Bs[c8*4+2][row]=vb.z; Bs[c8*4+3][row]=vb.w;
        }
        __syncthreads();
#pragma unroll
        for (int kk=0;kk<BK;kk++) {
            float a[8], b[8];
            *(float4*)(a  ) = *(float4*)&As[kk][ty*8];
            *(float4*)(a+4) = *(float4*)&As[kk][ty*8+4];
            *(float4*)(b  ) = *(float4*)&Bs[kk][tx*8];
            *(float4*)(b+4) = *(float4*)&Bs[kk][tx*8+4];
#pragma unroll
            for (int i=0;i<8;i++)
#pragma unroll
                for (int j=0;j<8;j++) acc[i][j] += a[i]*b[j];
        }
        __syncthreads();
    }
#pragma unroll
    for (int i=0;i<8;i++) {
        int r = ty*8+i;
#pragma unroll
        for (int j=0;j<8;j+=2) {
            __nv_bfloat162 hp, lp;
            split2(acc[i][j], acc[i][j+1], hp, lp);
            int c = tx*8 + j;
            __nv_bfloat16* base = Cb + (size_t)r*KCAT + c;
            *(__nv_bfloat162*)(base)       = hp;
            *(__nv_bfloat162*)(base + 128) = (which==0) ? hp : lp;
            *(__nv_bfloat162*)(base + 256) = (which==0) ? lp : hp;
        }
    }
}

// ---------------- E = exp(H1cat @ H2cat^T - C), bf16 hi/lo + partial sums --
#define STS 72
__global__ __launch_bounds__(256,1) void gemm_s_exp(
    const __nv_bfloat16* __restrict__ Acat,
    const __nv_bfloat16* __restrict__ Bcat,
    __nv_bfloat16* __restrict__ Eh, __nv_bfloat16* __restrict__ El,
    float* __restrict__ rowp, float* __restrict__ colp)
{
    __shared__ __align__(16) __nv_bfloat16 As[128*STS];
    __shared__ __align__(16) __nv_bfloat16 Bs[128*STS];
    __shared__ float rowsum[128], colsum[128];
    int b = blockIdx.z, bx = blockIdx.x, by = blockIdx.y;
    const __nv_bfloat16* Ab = Acat + (size_t)b*NN*KCAT + (size_t)bx*128*KCAT;
    const __nv_bfloat16* Bb = Bcat + (size_t)b*NN*KCAT + (size_t)by*128*KCAT;
    __nv_bfloat16* Ehb = Eh + (size_t)b*NN*NN + (size_t)bx*128*NN + by*128;
    __nv_bfloat16* Elb = El + (size_t)b*NN*NN + (size_t)bx*128*NN + by*128;
    int tid = threadIdx.x, lane = tid & 31, w = tid >> 5;
    int wr = (w>>2)*64, wc = (w&3)*32;
    uint32_t aB = cvta_s(As), bB = cvta_s(Bs);
    int lrow = lane & 15, lcol = (lane>>4)*8;
    float acc[4][4][4];
#pragma unroll
    for (int i=0;i<4;i++)
#pragma unroll
        for (int j=0;j<4;j++)
#pragma unroll
            for (int r=0;r<4;r++) acc[i][j][r]=0.f;
    if (tid < 128) { rowsum[tid]=0.f; colsum[tid]=0.f; }

    int row = tid >> 1, part = tid & 1;
    for (int k0=0;k0<KCAT;k0+=64) {
        const int4* ga = (const int4*)(Ab + (size_t)row*KCAT + k0 + part*32);
        const int4* gb = (const int4*)(Bb + (size_t)row*KCAT + k0 + part*32);
        int4* sa = (int4*)(As + row*STS + part*32);
        int4* sb = (int4*)(Bs + row*STS + part*32);
        sa[0]=ga[0]; sa[1]=ga[1]; sa[2]=ga[2]; sa[3]=ga[3];
        sb[0]=gb[0]; sb[1]=gb[1]; sb[2]=gb[2]; sb[3]=gb[3];
        __syncthreads();
#pragma unroll
        for (int ks=0; ks<4; ks++) {
            int kk = ks*16;
            uint32_t af[4][4], bf[2][4];
#pragma unroll
            for (int mi=0;mi<4;mi++)
                ldsm4(af[mi], aB + (uint32_t)(((wr+mi*16+lrow)*STS + kk + lcol)*2));
#pragma unroll
            for (int nj=0;nj<2;nj++)
                ldsm4(bf[nj], bB + (uint32_t)(((wc+nj*16+lrow)*STS + kk + lcol)*2));
#pragma unroll
            for (int mi=0;mi<4;mi++)
#pragma unroll
                for (int ni=0;ni<4;ni++) {
                    uint32_t bb[2] = { bf[ni>>1][ni&1], bf[ni>>1][(ni&1)+2] };
                    mma16816(acc[mi][ni], af[mi], bb);
                }
        }
        __syncthreads();
    }

    int g = lane>>2, tg = lane&3;
    float colA[4]={0,0,0,0}, colB[4]={0,0,0,0};
#pragma unroll
    for (int mi=0;mi<4;mi++) {
        int r0 = wr + mi*16 + g;
        float rs0 = 0.f, rs1 = 0.f;
#pragma unroll
        for (int ni=0;ni<4;ni++) {
            int c = wc + ni*8 + 2*tg;
            float e0=__expf(acc[mi][ni][0]-CSHIFT), e1=__expf(acc[mi][ni][1]-CSHIFT);
            float e2=__expf(acc[mi][ni][2]-CSHIFT), e3=__expf(acc[mi][ni][3]-CSHIFT);
            __nv_bfloat162 hp, lp;
            split2(e0,e1,hp,lp);
            *(__nv_bfloat162*)(Ehb + (size_t)r0*NN + c) = hp;
            *(__nv_bfloat162*)(Elb + (size_t)r0*NN + c) = lp;
            split2(e2,e3,hp,lp);
            *(__nv_bfloat162*)(Ehb + (size_t)(r0+8)*NN + c) = hp;
            *(__nv_bfloat162*)(Elb + (size_t)(r0+8)*NN + c) = lp;
            rs0 += e0+e1; rs1 += e2+e3;
            colA[ni] += e0+e2; colB[ni] += e1+e3;
        }
        atomicAdd(&rowsum[r0 - 0], rs0);
        atomicAdd(&rowsum[r0 + 8], rs1);
    }
#pragma unroll
    for (int ni=0;ni<4;ni++) {
        int c = wc + ni*8 + 2*tg;
        atomicAdd(&colsum[c],   colA[ni]);
        atomicAdd(&colsum[c+1], colB[ni]);
    }
    __syncthreads();
    if (tid < 128) {
        rowp[((size_t)(b*16+by))*NN + bx*128 + tid] = rowsum[tid];
        colp[((size_t)(b*16+bx))*NN + by*128 + tid] = colsum[tid];
    }
}

// ---------------- combine partials -> reciprocals --------------------------
__global__ void combine_stats(const float* __restrict__ rowp,
                              const float* __restrict__ colp,
                              float* __restrict__ rzi, float* __restrict__ czi)
{
    int idx = blockIdx.x*256 + threadIdx.x;   // [0, B*N)
    int b = idx >> 11, n = idx & (NN-1);
    float zr = 0.f, zc = 0.f;
#pragma unroll
    for (int t=0;t<16;t++) {
        zr += rowp[((size_t)(b*16+t))*NN + n];
        zc += colp[((size_t)(b*16+t))*NN + n];
    }
    rzi[idx] = 1.f/zr;
    czi[idx] = 1.f/zc;
}

// ---------------- V prep: scale, transpose to [k][m], split hi/lo ----------
// z in [0,16): which = z>>3 (0: V2*czi -> Vt2, 1: V1*rzi -> Vt1), b = z&7
__global__ __launch_bounds__(256,1) void vprep(
    const float* __restrict__ V2, const float* __restrict__ czi,
    const float* __restrict__ V1, const float* __restrict__ rzi,
    __nv_bfloat16* __restrict__ Vt2h, __nv_bfloat16* __restrict__ Vt2l,
    __nv_bfloat16* __restrict__ Vt1h, __nv_bfloat16* __restrict__ Vt1l)
{
    __shared__ float sh[32][132];
    int which = blockIdx.z >> 3, b = blockIdx.z & 7;
    const float* Vb = (which==0 ? V2 : V1) + (size_t)b*NN*DD;
    const float* sb = (which==0 ? czi : rzi) + b*NN;
    __nv_bfloat16* Vth = (which==0 ? Vt2h : Vt1h);
    __nv_bfloat16* Vtl = (which==0 ? Vt2l : Vt1l);
    int m0 = blockIdx.x*32;
    int tid = threadIdx.x;
    {
        int r = tid>>3, c16 = (tid&7)*16;
        float s = sb[m0+r];
        const float4* g = (const float4*)(Vb + (size_t)(m0+r)*DD + c16);
#pragma unroll
        for (int q=0;q<4;q++) {
            float4 v = g[q];
            v.x*=s; v.y*=s; v.z*=s; v.w*=s;
            *(float4*)&sh[r][c16+q*4] = v;
        }
    }
    __syncthreads();
    {
        int k = tid>>1, half = tid&1;
        union { __nv_bfloat16 bh[16]; int4 v4[2]; } uh, ul;
#pragma unroll
        for (int j=0;j<16;j++) {
            float f = sh[half*16+j][k];
            __nv_bfloat16 h = __float2bfloat16(f);
            uh.bh[j] = h;
            ul.bh[j] = __float2bfloat16(f - __bfloat162float(h));
        }
        __nv_bfloat16* oh = Vth + (size_t)b*DD*NN + (size_t)k*NN + m0 + half*16;
        __nv_bfloat16* ol = Vtl + (size_t)b*DD*NN + (size_t)k*NN + m0 + half*16;
        ((int4*)oh)[0]=uh.v4[0]; ((int4*)oh)[1]=uh.v4[1];
        ((int4*)ol)[0]=ul.v4[0]; ((int4*)ol)[1]=ul.v4[1];
    }
}

// ---------------- AV via tensor cores (both modes in one launch) -----------
// mode = blockIdx.y
// mode 0: Out[n,k] = sum_m E[n,m] * Vt2[k][m]   (A natural layout)
// mode 1: Out[m,k] = sum_n E[n,m] * Vt1[k][n]   (A via ldmatrix.trans)
#define STA 40
#define STT 136
__global__ __launch_bounds__(256,1) void attn_av_bf16(
    const __nv_bfloat16* __restrict__ Eh, const __nv_bfloat16* __restrict__ El,
    const __nv_bfloat16* __restrict__ Vt2h, const __nv_bfloat16* __restrict__ Vt2l,
    const __nv_bfloat16* __restrict__ Vt1h, const __nv_bfloat16* __restrict__ Vt1l,
    float* __restrict__ N12, float* __restrict__ N21)
{
    __shared__ __align__(16) __nv_bfloat16 Ah[5120];
    __shared__ __align__(16) __nv_bfloat16 Al[5120];
    __shared__ __align__(16) __nv_bfloat16 Bh[5120];
    __shared__ __align__(16) __nv_bfloat16 Bl[5120];
    int b = blockIdx.z, mode = blockIdx.y;
    const __nv_bfloat16* Ehb = Eh + (size_t)b*NN*NN;
    const __nv_bfloat16* Elb = El + (size_t)b*NN*NN;
    const __nv_bfloat16* Vhb = (mode==0 ? Vt2h : Vt1h) + (size_t)b*DD*NN;
    const __nv_bfloat16* Vlb = (mode==0 ? Vt2l : Vt1l) + (size_t)b*DD*NN;
    int rb = blockIdx.x*128;
    float* Ob = (mode==0 ? N12 : N21) + (size_t)b*NN*DD + (size_t)rb*DD;
    int tid = threadIdx.x, lane = tid & 31, w = tid >> 5;
    int wr = (w&3)*32, wc = (w>>2)*64;
    uint32_t aB = cvta_s(Ah), alB = cvta_s(Al), bB = cvta_s(Bh), blB = cvta_s(Bl);
    int lrow = lane & 15, lcol = (lane>>4)*8;
    int trow = (lane&7) + ((lane>>4)<<3);
    int tcol = ((lane>>3)&1)*8;
    float acc[2][8][4];
#pragma unroll
    for (int i=0;i<2;i++)
#pragma unroll
        for (int j=0;j<8;j++)
#pragma unroll
            for (int r=0;r<4;r++) acc[i][j][r]=0.f;

    for (int p0=0;p0<NN;p0+=32) {
        if (mode==0) {
            // A tile: E rows [rb, rb+128) x cols [p0, p0+32)
            int r = tid>>1, part = tid&1;
            const int4* gh = (const int4*)(Ehb + (size_t)(rb+r)*NN + p0 + part*16);
            const int4* gl = (const int4*)(Elb + (size_t)(rb+r)*NN + p0 + part*16);
            int4* sh = (int4*)(Ah + r*STA + part*16);
            int4* sl = (int4*)(Al + r*STA + part*16);
            sh[0]=gh[0]; sh[1]=gh[1];
            sl[0]=gl[0]; sl[1]=gl[1];
        } else {
            // A tile (transposed use): E rows [p0, p0+32) x cols [rb, rb+128)
            int r = tid>>3, cb = (tid&7)*16;
            const int4* gh = (const int4*)(Ehb + (size_t)(p0+r)*NN + rb + cb);
            const int4* gl = (const int4*)(Elb + (size_t)(p0+r)*NN + rb + cb);
            int4* sh = (int4*)(Ah + r*STT + cb);
            int4* sl = (int4*)(Al + r*STT + cb);
            sh[0]=gh[0]; sh[1]=gh[1];
            sl[0]=gl[0]; sl[1]=gl[1];
        }
        {
            int r = tid>>1, part = tid&1;
            const int4* gh = (const int4*)(Vhb + (size_t)r*NN + p0 + part*16);
            const int4* gl = (const int4*)(Vlb + (size_t)r*NN + p0 + part*16);
            int4* sh = (int4*)(Bh + r*STA + part*16);
            int4* sl = (int4*)(Bl + r*STA + part*16);
            sh[0]=gh[0]; sh[1]=gh[1];
            sl[0]=gl[0]; sl[1]=gl[1];
        }
        __syncthreads();
#pragma unroll
        for (int pass=0; pass<3; pass++) {
            uint32_t aBase = (pass<2) ? aB : alB;
            uint32_t bBase = (pass==1) ? blB : bB;
#pragma unroll
            for (int ks=0; ks<2; ks++) {
                int kk = ks*16;
                uint32_t af[2][4], bf[4][4];
#pragma unroll
                for (int mi=0;mi<2;mi++) {
                    if (mode==0)
                        ldsm4 (af[mi], aBase + (uint32_t)(((wr+mi*16+lrow)*STA + kk + lcol)*2));
                    else
                        ldsm4t(af[mi], aBase + (uint32_t)(((kk+trow)*STT + wr + mi*16 + tcol)*2));
                }
#pragma unroll
                for (int nj=0;nj<4;nj++)
                    ldsm4(bf[nj], bBase + (uint32_t)(((wc+nj*16+lrow)*STA + kk + lcol)*2));
#pragma unroll
                for (int mi=0;mi<2;mi++)
#pragma unroll
                    for (int ni=0;ni<8;ni++) {
                        uint32_t bb[2] = { bf[ni>>1][ni&1], bf[ni>>1][(ni&1)+2] };
                        mma16816(acc[mi][ni], af[mi], bb);
                    }
            }
        }
        __syncthreads();
    }
    int g = lane>>2, tg = lane&3;
#pragma unroll
    for (int mi=0;mi<2;mi++)
#pragma unroll
        for (int ni=0;ni<8;ni++) {
            int r0 = wr + mi*16 + g, c = wc + ni*8 + 2*tg;
            *(float2*)(Ob + (size_t)r0*DD + c)     = make_float2(acc[mi][ni][0], acc[mi][ni][1]);
            *(float2*)(Ob + (size_t)(r0+8)*DD + c) = make_float2(acc[mi][ni][2], acc[mi][ni][3]);
        }
}

// ---------------- launch ---------------------------------------------------
extern "C" void kernel_launch(void* const* d_in, const int* in_sizes, int n_in,
                              void* d_out, int out_size)
{
    const float* x1 = (const float*)d_in[0];
    const float* x2 = (const float*)d_in[1];
    const float* Wk = (const float*)d_in[2];
    const float* Wv = (const float*)d_in[3];
    const float* Wo = (const float*)d_in[4];
    const float* bo = (const float*)d_in[5];
    float* msg1 = (float*)d_out;
    float* msg2 = msg1 + (size_t)BB*NN*DD;

    __nv_bfloat16 *H1c,*H2c,*Eh,*El,*Vt1h,*Vt1l,*Vt2h,*Vt2l;
    float *V1,*V2,*rowp,*colp,*rzi,*czi,*N12,*N21;
    cudaGetSymbolAddress((void**)&H1c, g_H1cat);
    cudaGetSymbolAddress((void**)&H2c, g_H2cat);
    cudaGetSymbolAddress((void**)&V1,  g_V1);
    cudaGetSymbolAddress((void**)&V2,  g_V2);
    cudaGetSymbolAddress((void**)&Eh,  g_Eh);
    cudaGetSymbolAddress((void**)&El,  g_El);
    cudaGetSymbolAddress((void**)&rowp,g_rowp);
    cudaGetSymbolAddress((void**)&colp,g_colp);
    cudaGetSymbolAddress((void**)&rzi, g_rzi);
    cudaGetSymbolAddress((void**)&czi, g_czi);
    cudaGetSymbolAddress((void**)&Vt1h,g_Vt1h);
    cudaGetSymbolAddress((void**)&Vt1l,g_Vt1l);
    cudaGetSymbolAddress((void**)&Vt2h,g_Vt2h);
    cudaGetSymbolAddress((void**)&Vt2l,g_Vt2l);
    cudaGetSymbolAddress((void**)&N12, g_N12);
    cudaGetSymbolAddress((void**)&N21, g_N21);

    dim3 thr(256);

    // 1) projections: key -> bf16 cat (one launch), value -> fp32
    proj_cat_dual<<<dim3(128,1,2),thr>>>(x1, x2, Wk, H1c, H2c);
    gemm_tn<0><<<dim3(128,1,1),thr>>>(x1,Wv,V1,nullptr);
    gemm_tn<0><<<dim3(128,1,1),thr>>>(x2,Wv,V2,nullptr);

    // 2) E = exp(S - C) bf16 hi/lo + row/col partial sums (fused)
    gemm_s_exp<<<dim3(16,16,8),thr>>>(H1c, H2c, Eh, El, rowp, colp);

    // 3) combine partials
    combine_stats<<<64,256>>>(rowp, colp, rzi, czi);

    // 4) V scale+transpose+split (one launch), then AV both modes (one launch)
    vprep<<<dim3(64,1,16),thr>>>(V2, czi, V1, rzi, Vt2h, Vt2l, Vt1h, Vt1l);
    attn_av_bf16<<<dim3(16,2,8),thr>>>(Eh, El, Vt2h, Vt2l, Vt1h, Vt1l, N12, N21);

    // 5) output projection + bias + leaky relu (fp32)
    gemm_tn<1><<<dim3(128,1,1),thr>>>(N12,Wo,msg1,bo);
    gemm_tn<1><<<dim3(128,1,1),thr>>>(N21,Wo,msg2,bo);
}

// round 7
// speedup vs baseline: 1.7769x; 1.1503x over previous
#include <cuda_runtime.h>
#include <cuda_bf16.h>
#include <math.h>
#include <stdint.h>

#define BB 8
#define NN 2048
#define DD 128
#define KCAT 384
#define CSHIFT 80.0f

// ---------------- scratch (static device globals; no allocation) ----------
__device__ __nv_bfloat16 g_H1cat[(size_t)BB*NN*KCAT];  // [hi|hi|lo]
__device__ __nv_bfloat16 g_H2cat[(size_t)BB*NN*KCAT];  // [hi|lo|hi]
__device__ float g_V1[BB*NN*DD];
__device__ float g_V2[BB*NN*DD];
__device__ __nv_bfloat16 g_Eh[(size_t)BB*NN*NN];       // exp(S-C) hi, 67MB
__device__ __nv_bfloat16 g_El[(size_t)BB*NN*NN];       // exp(S-C) lo, 67MB
__device__ float g_rowp[(size_t)BB*16*NN], g_colp[(size_t)BB*16*NN];
__device__ float g_rzi[BB*NN], g_czi[BB*NN];
__device__ __nv_bfloat16 g_Vt1h[(size_t)BB*DD*NN], g_Vt1l[(size_t)BB*DD*NN];
__device__ __nv_bfloat16 g_Vt2h[(size_t)BB*DD*NN], g_Vt2l[(size_t)BB*DD*NN];
__device__ float g_N12[BB*NN*DD], g_N21[BB*NN*DD];

// ---------------- mma / ldmatrix / cp.async helpers ------------------------
__device__ __forceinline__ void mma16816(float* d, const uint32_t* a, const uint32_t* b){
    asm volatile(
        "mma.sync.aligned.m16n8k16.row.col.f32.bf16.bf16.f32 "
        "{%0,%1,%2,%3},{%4,%5,%6,%7},{%8,%9},{%0,%1,%2,%3};\n"
        : "+f"(d[0]),"+f"(d[1]),"+f"(d[2]),"+f"(d[3])
        : "r"(a[0]),"r"(a[1]),"r"(a[2]),"r"(a[3]),"r"(b[0]),"r"(b[1]));
}
__device__ __forceinline__ void ldsm4(uint32_t* r, uint32_t addr){
    asm volatile("ldmatrix.sync.aligned.m8n8.x4.shared.b16 {%0,%1,%2,%3},[%4];\n"
        :"=r"(r[0]),"=r"(r[1]),"=r"(r[2]),"=r"(r[3]):"r"(addr));
}
__device__ __forceinline__ void ldsm4t(uint32_t* r, uint32_t addr){
    asm volatile("ldmatrix.sync.aligned.m8n8.x4.trans.shared.b16 {%0,%1,%2,%3},[%4];\n"
        :"=r"(r[0]),"=r"(r[1]),"=r"(r[2]),"=r"(r[3]):"r"(addr));
}
__device__ __forceinline__ uint32_t cvta_s(const void* p){
    return (uint32_t)__cvta_generic_to_shared(p);
}
__device__ __forceinline__ void cpa16(uint32_t dst, const void* src){
    asm volatile("cp.async.cg.shared.global [%0], [%1], 16;\n"::"r"(dst),"l"(src));
}
__device__ __forceinline__ void cp_commit(){ asm volatile("cp.async.commit_group;\n"); }
template<int N> __device__ __forceinline__ void cp_wait(){
    asm volatile("cp.async.wait_group %0;\n"::"n"(N));
}
__device__ __forceinline__ void split2(float a, float b,
                                       __nv_bfloat162& hp, __nv_bfloat162& lp){
    __nv_bfloat16 ha=__float2bfloat16(a), hb=__float2bfloat16(b);
    hp.x=ha; hp.y=hb;
    lp.x=__float2bfloat16(a-__bfloat162float(ha));
    lp.y=__float2bfloat16(b-__bfloat162float(hb));
}

// ---------------- fp32 SIMT GEMM (V projections / epilogue) ----------------
#define BM 128
#define BN 128
#define BK 32
#define ASTR (BM+4)

template<int EPI>
__global__ __launch_bounds__(256,1) void gemm_tn(
    const float* __restrict__ A, const float* __restrict__ Bmat,
    float* __restrict__ C, const float* __restrict__ bias)
{
    __shared__ float As[BK][ASTR];
    __shared__ float Bs[BK][ASTR];
    const float* Ab = A + (long)blockIdx.x*BM*DD;
    float* Cb = C + (long)blockIdx.x*BM*DD;
    int tid = threadIdx.x;
    int tx = tid & 15, ty = tid >> 4;
    float acc[8][8];
#pragma unroll
    for (int i=0;i<8;i++)
#pragma unroll
        for (int j=0;j<8;j++) acc[i][j]=0.f;

    for (int k0=0;k0<DD;k0+=BK) {
#pragma unroll
        for (int i=0;i<4;i++) {
            int slot = tid + i*256;
            int row = slot >> 3, c8 = slot & 7;
            float4 va = *(const float4*)(Ab + (long)row*DD + k0 + c8*4);
            As[c8*4+0][row]=va.x; As[c8*4+1][row]=va.y;
            As[c8*4+2][row]=va.z; As[c8*4+3][row]=va.w;
            float4 vb = *(const float4*)(Bmat + (long)row*DD + k0 + c8*4);
            Bs[c8*4+0][row]=vb.x; Bs[c8*4+1][row]=vb.y;
            Bs[c8*4+2][row]=vb.z; Bs[c8*4+3][row]=vb.w;
        }
        __syncthreads();
#pragma unroll
        for (int kk=0;kk<BK;kk++) {
            float a[8], b[8];
            *(float4*)(a  ) = *(float4*)&As[kk][ty*8];
            *(float4*)(a+4) = *(float4*)&As[kk][ty*8+4];
            *(float4*)(b  ) = *(float4*)&Bs[kk][tx*8];
            *(float4*)(b+4) = *(float4*)&Bs[kk][tx*8+4];
#pragma unroll
            for (int i=0;i<8;i++)
#pragma unroll
                for (int j=0;j<8;j++) acc[i][j] += a[i]*b[j];
        }
        __syncthreads();
    }
#pragma unroll
    for (int i=0;i<8;i++) {
        int r = ty*8+i;
#pragma unroll
        for (int j=0;j<8;j+=4) {
            float4 v;
            v.x=acc[i][j]; v.y=acc[i][j+1]; v.z=acc[i][j+2]; v.w=acc[i][j+3];
            if (EPI==1) {
                int c = tx*8 + j;
                v.x += bias[c];   v.y += bias[c+1];
                v.z += bias[c+2]; v.w += bias[c+3];
                v.x = v.x>0.f? v.x : 0.01f*v.x;
                v.y = v.y>0.f? v.y : 0.01f*v.y;
                v.z = v.z>0.f? v.z : 0.01f*v.z;
                v.w = v.w>0.f? v.w : 0.01f*v.w;
            }
            *(float4*)(Cb + (long)r*DD + tx*8 + j) = v;
        }
    }
}

// ---------------- dual projection + hi/lo split into cat layout ------------
// z=0: x1 -> H1cat [hi|hi|lo];  z=1: x2 -> H2cat [hi|lo|hi]
__global__ __launch_bounds__(256,1) void proj_cat_dual(
    const float* __restrict__ X1, const float* __restrict__ X2,
    const float* __restrict__ W,
    __nv_bfloat16* __restrict__ H1c, __nv_bfloat16* __restrict__ H2c)
{
    __shared__ float As[BK][ASTR];
    __shared__ float Bs[BK][ASTR];
    int which = blockIdx.z;
    const float* Ab = (which==0 ? X1 : X2) + (long)blockIdx.x*BM*DD;
    __nv_bfloat16* Cb = (which==0 ? H1c : H2c) + (size_t)blockIdx.x*BM*KCAT;
    int tid = threadIdx.x;
    int tx = tid & 15, ty = tid >> 4;
    float acc[8][8];
#pragma unroll
    for (int i=0;i<8;i++)
#pragma unroll
        for (int j=0;j<8;j++) acc[i][j]=0.f;

    for (int k0=0;k0<DD;k0+=BK) {
#pragma unroll
        for (int i=0;i<4;i++) {
            int slot = tid + i*256;
            int row = slot >> 3, c8 = slot & 7;
            float4 va = *(const float4*)(Ab + (long)row*DD + k0 + c8*4);
            As[c8*4+0][row]=va.x; As[c8*4+1][row]=va.y;
            As[c8*4+2][row]=va.z; As[c8*4+3][row]=va.w;
            float4 vb = *(const float4*)(W + (long)row*DD + k0 + c8*4);
            Bs[c8*4+0][row]=vb.x; Bs[c8*4+1][row]=vb.y;
            Bs[c8*4+2][row]=vb.z; Bs[c8*4+3][row]=vb.w;
        }
        __syncthreads();
#pragma unroll
        for (int kk=0;kk<BK;kk++) {
            float a[8], b[8];
            *(float4*)(a  ) = *(float4*)&As[kk][ty*8];
            *(float4*)(a+4) = *(float4*)&As[kk][ty*8+4];
            *(float4*)(b  ) = *(float4*)&Bs[kk][tx*8];
            *(float4*)(b+4) = *(float4*)&Bs[kk][tx*8+4];
#pragma unroll
            for (int i=0;i<8;i++)
#pragma unroll
                for (int j=0;j<8;j++) acc[i][j] += a[i]*b[j];
        }
        __syncthreads();
    }
#pragma unroll
    for (int i=0;i<8;i++) {
        int r = ty*8+i;
#pragma unroll
        for (int j=0;j<8;j+=2) {
            __nv_bfloat162 hp, lp;
            split2(acc[i][j], acc[i][j+1], hp, lp);
            int c = tx*8 + j;
            __nv_bfloat16* base = Cb + (size_t)r*KCAT + c;
            *(__nv_bfloat162*)(base)       = hp;
            *(__nv_bfloat162*)(base + 128) = (which==0) ? hp : lp;
            *(__nv_bfloat162*)(base + 256) = (which==0) ? lp : hp;
        }
    }
}

// ---------------- E = exp(H1cat @ H2cat^T - C), pipelined ------------------
#define STS 72
#define SSTAGE (128*STS)            // elems per matrix per stage
__global__ __launch_bounds__(256,1) void gemm_s_exp(
    const __nv_bfloat16* __restrict__ Acat,
    const __nv_bfloat16* __restrict__ Bcat,
    __nv_bfloat16* __restrict__ Eh, __nv_bfloat16* __restrict__ El,
    float* __restrict__ rowp, float* __restrict__ colp)
{
    extern __shared__ __align__(16) char dyn_s[];
    __nv_bfloat16* As = (__nv_bfloat16*)dyn_s;           // [2][SSTAGE]
    __nv_bfloat16* Bs = As + 2*SSTAGE;                    // [2][SSTAGE]
    __shared__ float rowsum[128], colsum[128];
    int b = blockIdx.z, bx = blockIdx.x, by = blockIdx.y;
    const __nv_bfloat16* Ab = Acat + (size_t)b*NN*KCAT + (size_t)bx*128*KCAT;
    const __nv_bfloat16* Bb = Bcat + (size_t)b*NN*KCAT + (size_t)by*128*KCAT;
    __nv_bfloat16* Ehb = Eh + (size_t)b*NN*NN + (size_t)bx*128*NN + by*128;
    __nv_bfloat16* Elb = El + (size_t)b*NN*NN + (size_t)bx*128*NN + by*128;
    int tid = threadIdx.x, lane = tid & 31, w = tid >> 5;
    int wr = (w>>2)*64, wc = (w&3)*32;
    uint32_t aB0 = cvta_s(As), bB0 = cvta_s(Bs);
    int lrow = lane & 15, lcol = (lane>>4)*8;
    float acc[4][4][4];
#pragma unroll
    for (int i=0;i<4;i++)
#pragma unroll
        for (int j=0;j<4;j++)
#pragma unroll
            for (int r=0;r<4;r++) acc[i][j][r]=0.f;
    if (tid < 128) { rowsum[tid]=0.f; colsum[tid]=0.f; }

    int row = tid >> 1, part = tid & 1;
    uint32_t sa_off = (uint32_t)((row*STS + part*32)*2);
    uint32_t sb_off = sa_off;

    // pipeline: 6 iterations of K-chunk 64
#pragma unroll 1
    for (int it=-1; it<6; it++) {
        // issue stage it+1
        int nx = it+1;
        if (nx < 6) {
            int st = nx & 1;
            uint32_t sa = aB0 + (uint32_t)(st*SSTAGE*2) + sa_off;
            const __nv_bfloat16* ga = Ab + (size_t)row*KCAT + nx*64 + part*32;
            cpa16(sa,    ga);    cpa16(sa+16, ga+8);
            cpa16(sa+32, ga+16); cpa16(sa+48, ga+24);
            uint32_t sb = bB0 + (uint32_t)(st*SSTAGE*2) + sb_off;
            const __nv_bfloat16* gb = Bb + (size_t)row*KCAT + nx*64 + part*32;
            cpa16(sb,    gb);    cpa16(sb+16, gb+8);
            cpa16(sb+32, gb+16); cpa16(sb+48, gb+24);
            cp_commit();
        }
        if (it < 0) continue;
        if (nx < 6) cp_wait<1>(); else cp_wait<0>();
        __syncthreads();
        int st = it & 1;
        uint32_t aSt = aB0 + (uint32_t)(st*SSTAGE*2);
        uint32_t bSt = bB0 + (uint32_t)(st*SSTAGE*2);
#pragma unroll
        for (int ks=0; ks<4; ks++) {
            int kk = ks*16;
            uint32_t af[4][4], bf[2][4];
#pragma unroll
            for (int mi=0;mi<4;mi++)
                ldsm4(af[mi], aSt + (uint32_t)(((wr+mi*16+lrow)*STS + kk + lcol)*2));
#pragma unroll
            for (int nj=0;nj<2;nj++)
                ldsm4(bf[nj], bSt + (uint32_t)(((wc+nj*16+lrow)*STS + kk + lcol)*2));
#pragma unroll
            for (int mi=0;mi<4;mi++)
#pragma unroll
                for (int ni=0;ni<4;ni++) {
                    uint32_t bb[2] = { bf[ni>>1][ni&1], bf[ni>>1][(ni&1)+2] };
                    mma16816(acc[mi][ni], af[mi], bb);
                }
        }
        __syncthreads();
    }

    int g = lane>>2, tg = lane&3;
    float colA[4]={0,0,0,0}, colB[4]={0,0,0,0};
#pragma unroll
    for (int mi=0;mi<4;mi++) {
        int r0 = wr + mi*16 + g;
        float rs0 = 0.f, rs1 = 0.f;
#pragma unroll
        for (int ni=0;ni<4;ni++) {
            int c = wc + ni*8 + 2*tg;
            float e0=__expf(acc[mi][ni][0]-CSHIFT), e1=__expf(acc[mi][ni][1]-CSHIFT);
            float e2=__expf(acc[mi][ni][2]-CSHIFT), e3=__expf(acc[mi][ni][3]-CSHIFT);
            __nv_bfloat162 hp, lp;
            split2(e0,e1,hp,lp);
            *(__nv_bfloat162*)(Ehb + (size_t)r0*NN + c) = hp;
            *(__nv_bfloat162*)(Elb + (size_t)r0*NN + c) = lp;
            split2(e2,e3,hp,lp);
            *(__nv_bfloat162*)(Ehb + (size_t)(r0+8)*NN + c) = hp;
            *(__nv_bfloat162*)(Elb + (size_t)(r0+8)*NN + c) = lp;
            rs0 += e0+e1; rs1 += e2+e3;
            colA[ni] += e0+e2; colB[ni] += e1+e3;
        }
        atomicAdd(&rowsum[r0 - 0], rs0);
        atomicAdd(&rowsum[r0 + 8], rs1);
    }
#pragma unroll
    for (int ni=0;ni<4;ni++) {
        int c = wc + ni*8 + 2*tg;
        atomicAdd(&colsum[c],   colA[ni]);
        atomicAdd(&colsum[c+1], colB[ni]);
    }
    __syncthreads();
    if (tid < 128) {
        rowp[((size_t)(b*16+by))*NN + bx*128 + tid] = rowsum[tid];
        colp[((size_t)(b*16+bx))*NN + by*128 + tid] = colsum[tid];
    }
}

// ---------------- combine partials -> reciprocals --------------------------
__global__ void combine_stats(const float* __restrict__ rowp,
                              const float* __restrict__ colp,
                              float* __restrict__ rzi, float* __restrict__ czi)
{
    int idx = blockIdx.x*256 + threadIdx.x;   // [0, B*N)
    int b = idx >> 11, n = idx & (NN-1);
    float zr = 0.f, zc = 0.f;
#pragma unroll
    for (int t=0;t<16;t++) {
        zr += rowp[((size_t)(b*16+t))*NN + n];
        zc += colp[((size_t)(b*16+t))*NN + n];
    }
    rzi[idx] = 1.f/zr;
    czi[idx] = 1.f/zc;
}

// ---------------- V prep: scale, transpose to [k][m], split hi/lo ----------
__global__ __launch_bounds__(256,1) void vprep(
    const float* __restrict__ V2, const float* __restrict__ czi,
    const float* __restrict__ V1, const float* __restrict__ rzi,
    __nv_bfloat16* __restrict__ Vt2h, __nv_bfloat16* __restrict__ Vt2l,
    __nv_bfloat16* __restrict__ Vt1h, __nv_bfloat16* __restrict__ Vt1l)
{
    __shared__ float sh[32][132];
    int which = blockIdx.z >> 3, b = blockIdx.z & 7;
    const float* Vb = (which==0 ? V2 : V1) + (size_t)b*NN*DD;
    const float* sb = (which==0 ? czi : rzi) + b*NN;
    __nv_bfloat16* Vth = (which==0 ? Vt2h : Vt1h);
    __nv_bfloat16* Vtl = (which==0 ? Vt2l : Vt1l);
    int m0 = blockIdx.x*32;
    int tid = threadIdx.x;
    {
        int r = tid>>3, c16 = (tid&7)*16;
        float s = sb[m0+r];
        const float4* g = (const float4*)(Vb + (size_t)(m0+r)*DD + c16);
#pragma unroll
        for (int q=0;q<4;q++) {
            float4 v = g[q];
            v.x*=s; v.y*=s; v.z*=s; v.w*=s;
            *(float4*)&sh[r][c16+q*4] = v;
        }
    }
    __syncthreads();
    {
        int k = tid>>1, half = tid&1;
        union { __nv_bfloat16 bh[16]; int4 v4[2]; } uh, ul;
#pragma unroll
        for (int j=0;j<16;j++) {
            float f = sh[half*16+j][k];
            __nv_bfloat16 h = __float2bfloat16(f);
            uh.bh[j] = h;
            ul.bh[j] = __float2bfloat16(f - __bfloat162float(h));
        }
        __nv_bfloat16* oh = Vth + (size_t)b*DD*NN + (size_t)k*NN + m0 + half*16;
        __nv_bfloat16* ol = Vtl + (size_t)b*DD*NN + (size_t)k*NN + m0 + half*16;
        ((int4*)oh)[0]=uh.v4[0]; ((int4*)oh)[1]=uh.v4[1];
        ((int4*)ol)[0]=ul.v4[0]; ((int4*)ol)[1]=ul.v4[1];
    }
}

// ---------------- AV via tensor cores, pipelined ---------------------------
// mode 0: Out[n,k] = sum_m E[n,m] * Vt2[k][m]   (A natural layout)
// mode 1: Out[m,k] = sum_n E[n,m] * Vt1[k][n]   (A via ldmatrix.trans)
#define STA 40
#define STT 136
#define AVBUF 5120                   // elems per buffer (fits 128*STA and 32*STT)
__global__ __launch_bounds__(256,1) void attn_av_bf16(
    const __nv_bfloat16* __restrict__ Eh, const __nv_bfloat16* __restrict__ El,
    const __nv_bfloat16* __restrict__ Vt2h, const __nv_bfloat16* __restrict__ Vt2l,
    const __nv_bfloat16* __restrict__ Vt1h, const __nv_bfloat16* __restrict__ Vt1l,
    float* __restrict__ N12, float* __restrict__ N21)
{
    extern __shared__ __align__(16) char dyn_s[];
    // layout: [stage][buf: Ah=0, Al=1, Bh=2, Bl=3]
    int b = blockIdx.z, mode = blockIdx.y;
    const __nv_bfloat16* Ehb = Eh + (size_t)b*NN*NN;
    const __nv_bfloat16* Elb = El + (size_t)b*NN*NN;
    const __nv_bfloat16* Vhb = (mode==0 ? Vt2h : Vt1h) + (size_t)b*DD*NN;
    const __nv_bfloat16* Vlb = (mode==0 ? Vt2l : Vt1l) + (size_t)b*DD*NN;
    int rb = blockIdx.x*128;
    float* Ob = (mode==0 ? N12 : N21) + (size_t)b*NN*DD + (size_t)rb*DD;
    int tid = threadIdx.x, lane = tid & 31, w = tid >> 5;
    int wr = (w&3)*32, wc = (w>>2)*64;
    uint32_t base0 = cvta_s(dyn_s);
    int lrow = lane & 15, lcol = (lane>>4)*8;
    int trow = (lane&7) + ((lane>>4)<<3);
    int tcol = ((lane>>3)&1)*8;
    float acc[2][8][4];
#pragma unroll
    for (int i=0;i<2;i++)
#pragma unroll
        for (int j=0;j<8;j++)
#pragma unroll
            for (int r=0;r<4;r++) acc[i][j][r]=0.f;

    // precomputed per-thread load offsets
    int ar = tid>>1, apart = tid&1;            // mode0 A + B loads
    int tr = tid>>3; int tcb = (tid&7)*16;     // mode1 A loads

#pragma unroll 1
    for (int it=-1; it<64; it++) {
        int nx = it+1;
        if (nx < 64) {
            int st = nx & 1;
            int p0 = nx*32;
            uint32_t stB = base0 + (uint32_t)(st*4*AVBUF*2);
            if (mode==0) {
                const __nv_bfloat16* gh = Ehb + (size_t)(rb+ar)*NN + p0 + apart*16;
                const __nv_bfloat16* gl = Elb + (size_t)(rb+ar)*NN + p0 + apart*16;
                uint32_t sa = stB + (uint32_t)((ar*STA + apart*16)*2);
                cpa16(sa, gh); cpa16(sa+16, gh+8);
                uint32_t sl = sa + (uint32_t)(AVBUF*2);
                cpa16(sl, gl); cpa16(sl+16, gl+8);
            } else {
                const __nv_bfloat16* gh = Ehb + (size_t)(p0+tr)*NN + rb + tcb;
                const __nv_bfloat16* gl = Elb + (size_t)(p0+tr)*NN + rb + tcb;
                uint32_t sa = stB + (uint32_t)((tr*STT + tcb)*2);
                cpa16(sa, gh); cpa16(sa+16, gh+8);
                uint32_t sl = sa + (uint32_t)(AVBUF*2);
                cpa16(sl, gl); cpa16(sl+16, gl+8);
            }
            {
                const __nv_bfloat16* gh = Vhb + (size_t)ar*NN + p0 + apart*16;
                const __nv_bfloat16* gl = Vlb + (size_t)ar*NN + p0 + apart*16;
                uint32_t sb = stB + (uint32_t)(2*AVBUF*2) + (uint32_t)((ar*STA + apart*16)*2);
                cpa16(sb, gh); cpa16(sb+16, gh+8);
                uint32_t sl = sb + (uint32_t)(AVBUF*2);
                cpa16(sl, gl); cpa16(sl+16, gl+8);
            }
            cp_commit();
        }
        if (it < 0) continue;
        if (nx < 64) cp_wait<1>(); else cp_wait<0>();
        __syncthreads();
        int st = it & 1;
        uint32_t stB = base0 + (uint32_t)(st*4*AVBUF*2);
        uint32_t aB  = stB;
        uint32_t alB = stB + (uint32_t)(AVBUF*2);
        uint32_t bB  = stB + (uint32_t)(2*AVBUF*2);
        uint32_t blB = stB + (uint32_t)(3*AVBUF*2);
#pragma unroll
        for (int pass=0; pass<3; pass++) {
            uint32_t aBase = (pass<2) ? aB : alB;
            uint32_t bBase = (pass==1) ? blB : bB;
#pragma unroll
            for (int ks=0; ks<2; ks++) {
                int kk = ks*16;
                uint32_t af[2][4], bf[4][4];
#pragma unroll
                for (int mi=0;mi<2;mi++) {
                    if (mode==0)
                        ldsm4 (af[mi], aBase + (uint32_t)(((wr+mi*16+lrow)*STA + kk + lcol)*2));
                    else
                        ldsm4t(af[mi], aBase + (uint32_t)(((kk+trow)*STT + wr + mi*16 + tcol)*2));
                }
#pragma unroll
                for (int nj=0;nj<4;nj++)
                    ldsm4(bf[nj], bBase + (uint32_t)(((wc+nj*16+lrow)*STA + kk + lcol)*2));
#pragma unroll
                for (int mi=0;mi<2;mi++)
#pragma unroll
                    for (int ni=0;ni<8;ni++) {
                        uint32_t bb[2] = { bf[ni>>1][ni&1], bf[ni>>1][(ni&1)+2] };
                        mma16816(acc[mi][ni], af[mi], bb);
                    }
            }
        }
        __syncthreads();
    }
    int g = lane>>2, tg = lane&3;
#pragma unroll
    for (int mi=0;mi<2;mi++)
#pragma unroll
        for (int ni=0;ni<8;ni++) {
            int r0 = wr + mi*16 + g, c = wc + ni*8 + 2*tg;
            *(float2*)(Ob + (size_t)r0*DD + c)     = make_float2(acc[mi][ni][0], acc[mi][ni][1]);
            *(float2*)(Ob + (size_t)(r0+8)*DD + c) = make_float2(acc[mi][ni][2], acc[mi][ni][3]);
        }
}

// ---------------- launch ---------------------------------------------------
extern "C" void kernel_launch(void* const* d_in, const int* in_sizes, int n_in,
                              void* d_out, int out_size)
{
    const float* x1 = (const float*)d_in[0];
    const float* x2 = (const float*)d_in[1];
    const float* Wk = (const float*)d_in[2];
    const float* Wv = (const float*)d_in[3];
    const float* Wo = (const float*)d_in[4];
    const float* bo = (const float*)d_in[5];
    float* msg1 = (float*)d_out;
    float* msg2 = msg1 + (size_t)BB*NN*DD;

    __nv_bfloat16 *H1c,*H2c,*Eh,*El,*Vt1h,*Vt1l,*Vt2h,*Vt2l;
    float *V1,*V2,*rowp,*colp,*rzi,*czi,*N12,*N21;
    cudaGetSymbolAddress((void**)&H1c, g_H1cat);
    cudaGetSymbolAddress((void**)&H2c, g_H2cat);
    cudaGetSymbolAddress((void**)&V1,  g_V1);
    cudaGetSymbolAddress((void**)&V2,  g_V2);
    cudaGetSymbolAddress((void**)&Eh,  g_Eh);
    cudaGetSymbolAddress((void**)&El,  g_El);
    cudaGetSymbolAddress((void**)&rowp,g_rowp);
    cudaGetSymbolAddress((void**)&colp,g_colp);
    cudaGetSymbolAddress((void**)&rzi, g_rzi);
    cudaGetSymbolAddress((void**)&czi, g_czi);
    cudaGetSymbolAddress((void**)&Vt1h,g_Vt1h);
    cudaGetSymbolAddress((void**)&Vt1l,g_Vt1l);
    cudaGetSymbolAddress((void**)&Vt2h,g_Vt2h);
    cudaGetSymbolAddress((void**)&Vt2l,g_Vt2l);
    cudaGetSymbolAddress((void**)&N12, g_N12);
    cudaGetSymbolAddress((void**)&N21, g_N21);

    // opt-in dynamic smem (idempotent; host-side, not stream-ordered)
    const int S_DYN  = 2*2*SSTAGE*2;           // 73728 B
    const int AV_DYN = 2*4*AVBUF*2;            // 81920 B
    static bool attr_done = false;
    if (!attr_done) {
        cudaFuncSetAttribute(gemm_s_exp,   cudaFuncAttributeMaxDynamicSharedMemorySize, S_DYN);
        cudaFuncSetAttribute(attn_av_bf16, cudaFuncAttributeMaxDynamicSharedMemorySize, AV_DYN);
        attr_done = true;
    }

    dim3 thr(256);

    // 1) projections: key -> bf16 cat (one launch), value -> fp32
    proj_cat_dual<<<dim3(128,1,2),thr>>>(x1, x2, Wk, H1c, H2c);
    gemm_tn<0><<<dim3(128,1,1),thr>>>(x1,Wv,V1,nullptr);
    gemm_tn<0><<<dim3(128,1,1),thr>>>(x2,Wv,V2,nullptr);

    // 2) E = exp(S - C) bf16 hi/lo + row/col partial sums (fused, pipelined)
    gemm_s_exp<<<dim3(16,16,8),thr,S_DYN>>>(H1c, H2c, Eh, El, rowp, colp);

    // 3) combine partials
    combine_stats<<<64,256>>>(rowp, colp, rzi, czi);

    // 4) V scale+transpose+split, then AV both modes (pipelined)
    vprep<<<dim3(64,1,16),thr>>>(V2, czi, V1, rzi, Vt2h, Vt2l, Vt1h, Vt1l);
    attn_av_bf16<<<dim3(16,2,8),thr,AV_DYN>>>(Eh, El, Vt2h, Vt2l, Vt1h, Vt1l, N12, N21);

    // 5) output projection + bias + leaky relu (fp32)
    gemm_tn<1><<<dim3(128,1,1),thr>>>(N12,Wo,msg1,bo);
    gemm_tn<1><<<dim3(128,1,1),thr>>>(N21,Wo,msg2,bo);
}